// round 1
// baseline (speedup 1.0000x reference)
#include <cuda_runtime.h>
#include <math_constants.h>

#define BATCH 16
#define NPTS  4096
#define GPTS  1024
#define D1    128
#define D2    256
#define CIN   384
#define CH    256
#define COUT  256
#define BN_EPS 1e-5f

// ---------------- scratch (device globals; no runtime allocation) ----------
__device__ float g_Xbuf[(size_t)BATCH * CIN * NPTS];   // assembled conv1 input [B][384][N]
__device__ float g_Y1  [(size_t)BATCH * CH  * NPTS];   // conv1 pre-BN output   [B][256][N]
__device__ float g_f2t [(size_t)BATCH * GPTS * D2];    // feature2 transposed   [B][G][256]
__device__ float g_sum1[CH],   g_sumsq1[CH];
__device__ float g_sum2[COUT], g_sumsq2[COUT];
__device__ float g_scale1[CH],   g_shift1[CH];
__device__ float g_scale2[COUT], g_shift2[COUT];

// ---------------- init: zero the stat accumulators --------------------------
__global__ void init_kernel() {
    int t = threadIdx.x;
    g_sum1[t] = 0.f; g_sumsq1[t] = 0.f;
    g_sum2[t] = 0.f; g_sumsq2[t] = 0.f;
}

// ---------------- transpose feature2: [B][D2][G] -> [B][G][D2] --------------
__global__ void transpose_f2_kernel(const float* __restrict__ f2) {
    __shared__ float tile[32][33];
    int b  = blockIdx.z;
    int g0 = blockIdx.x * 32;
    int d0 = blockIdx.y * 32;
    const float* src = f2 + (size_t)b * D2 * GPTS;
    #pragma unroll
    for (int r = threadIdx.y; r < 32; r += 8)
        tile[r][threadIdx.x] = src[(size_t)(d0 + r) * GPTS + g0 + threadIdx.x];
    __syncthreads();
    float* dst = g_f2t + (size_t)b * GPTS * D2;
    #pragma unroll
    for (int r = threadIdx.y; r < 32; r += 8)
        dst[(size_t)(g0 + r) * D2 + d0 + threadIdx.x] = tile[threadIdx.x][r];
}

// ---------------- 3-NN + interpolation + feature1 copy ----------------------
// One thread per query point n. Writes g_Xbuf[b][0:128][n] = feature1,
// g_Xbuf[b][128:384][n] = inverse-distance-weighted 3-NN interp of feature2.
__global__ void knn_interp_kernel(const float* __restrict__ coord1,
                                  const float* __restrict__ coord2,
                                  const float* __restrict__ feature1) {
    __shared__ float s2x[GPTS], s2y[GPTS], s2z[GPTS], s2n[GPTS];
    const int b = blockIdx.y;
    const int n = blockIdx.x * 128 + threadIdx.x;

    const float* c2 = coord2 + (size_t)b * 3 * GPTS;
    for (int g = threadIdx.x; g < GPTS; g += 128) {
        float x = c2[g], y = c2[GPTS + g], z = c2[2 * GPTS + g];
        s2x[g] = x; s2y[g] = y; s2z[g] = z;
        s2n[g] = x * x + y * y + z * z;
    }
    __syncthreads();

    const float* c1 = coord1 + (size_t)b * 3 * NPTS;
    const float x = c1[n], y = c1[NPTS + n], z = c1[2 * NPTS + n];
    const float q = x * x + y * y + z * z;

    float d0 = CUDART_INF_F, d1 = CUDART_INF_F, d2 = CUDART_INF_F;
    int   i0 = 0, i1 = 0, i2 = 0;
    #pragma unroll 4
    for (int g = 0; g < GPTS; ++g) {
        float dot  = x * s2x[g] + y * s2y[g] + z * s2z[g];
        float dist = q + s2n[g] - 2.0f * dot;
        if (dist < d2) {
            if (dist < d1) {
                d2 = d1; i2 = i1;
                if (dist < d0) { d1 = d0; i1 = i0; d0 = dist; i0 = g; }
                else           { d1 = dist; i1 = g; }
            } else { d2 = dist; i2 = g; }
        }
    }

    const float r0 = 1.0f / (d0 + 1e-8f);
    const float r1 = 1.0f / (d1 + 1e-8f);
    const float r2 = 1.0f / (d2 + 1e-8f);
    const float rs = 1.0f / (r0 + r1 + r2);
    const float w0 = r0 * rs, w1 = r1 * rs, w2 = r2 * rs;

    // copy feature1 -> channels [0,128)
    const float* f1 = feature1 + (size_t)b * D1 * NPTS + n;
    float* X0 = g_Xbuf + (size_t)b * CIN * NPTS + n;
    #pragma unroll 8
    for (int d = 0; d < D1; ++d) X0[(size_t)d * NPTS] = f1[(size_t)d * NPTS];

    // interp -> channels [128,384)
    const float* F = g_f2t + (size_t)b * GPTS * D2;
    const float4* p0 = (const float4*)(F + (size_t)i0 * D2);
    const float4* p1 = (const float4*)(F + (size_t)i1 * D2);
    const float4* p2 = (const float4*)(F + (size_t)i2 * D2);
    float* Xi = g_Xbuf + ((size_t)b * CIN + D1) * NPTS + n;
    #pragma unroll 4
    for (int d4 = 0; d4 < D2 / 4; ++d4) {
        float4 a = p0[d4], c = p1[d4], e = p2[d4];
        Xi[(size_t)(d4 * 4 + 0) * NPTS] = w0 * a.x + w1 * c.x + w2 * e.x;
        Xi[(size_t)(d4 * 4 + 1) * NPTS] = w0 * a.y + w1 * c.y + w2 * e.y;
        Xi[(size_t)(d4 * 4 + 2) * NPTS] = w0 * a.z + w1 * c.z + w2 * e.z;
        Xi[(size_t)(d4 * 4 + 3) * NPTS] = w0 * a.w + w1 * c.w + w2 * e.w;
    }
}

// ---------------- fp32 register-tiled GEMM body ------------------------------
// C[b][m][n] = sum_k W[m][k] * X[b][k][n] + bias[m]
// Optionally applies y = relu(x*scale[k]+shift[k]) to X elements on load (BN1
// folded into GEMM2's A-operand read).
// Block tile 128(M) x 128(N), K-tile 8, 256 threads, 8x8 per thread.
template <int K, bool BNIN>
__device__ __forceinline__ void gemm_body(const float* __restrict__ W,
                                          const float* __restrict__ X,
                                          const float* __restrict__ bias,
                                          const float* __restrict__ scl,
                                          const float* __restrict__ shf,
                                          float* __restrict__ C) {
    __shared__ float As[8][128];
    __shared__ float Bs[8][128];

    const int tid  = threadIdx.x;
    const int bcol = blockIdx.x;               // 0..511
    const int b    = bcol >> 5;                // 32 col-blocks per batch
    const int n0   = (bcol & 31) << 7;
    const int m0   = blockIdx.y << 7;

    const float* Xp = X + (size_t)b * K * NPTS + n0;

    const int lk = tid >> 5;                   // Bs row (0..7), one row per warp
    const int lj = (tid & 31) << 2;            // Bs col*4
    const int tx = tid & 15, ty = tid >> 4;

    float acc[8][8];
    #pragma unroll
    for (int i = 0; i < 8; ++i)
        #pragma unroll
        for (int j = 0; j < 8; ++j) acc[i][j] = 0.f;

    for (int k0 = 0; k0 < K; k0 += 8) {
        #pragma unroll
        for (int l = 0; l < 4; ++l) {
            int idx = tid + l * 256;
            int ak = idx >> 7, ai = idx & 127;
            As[ak][ai] = W[(size_t)(m0 + ai) * K + k0 + ak];
        }
        float4 v = *(const float4*)(Xp + (size_t)(k0 + lk) * NPTS + lj);
        if (BNIN) {
            float s = scl[k0 + lk], t = shf[k0 + lk];
            v.x = fmaxf(fmaf(v.x, s, t), 0.f);
            v.y = fmaxf(fmaf(v.y, s, t), 0.f);
            v.z = fmaxf(fmaf(v.z, s, t), 0.f);
            v.w = fmaxf(fmaf(v.w, s, t), 0.f);
        }
        *(float4*)&Bs[lk][lj] = v;
        __syncthreads();

        #pragma unroll
        for (int kk = 0; kk < 8; ++kk) {
            float a[8], bb[8];
            *(float4*)(a)      = *(const float4*)&As[kk][ty * 8];
            *(float4*)(a + 4)  = *(const float4*)&As[kk][ty * 8 + 4];
            *(float4*)(bb)     = *(const float4*)&Bs[kk][tx * 8];
            *(float4*)(bb + 4) = *(const float4*)&Bs[kk][tx * 8 + 4];
            #pragma unroll
            for (int i = 0; i < 8; ++i)
                #pragma unroll
                for (int j = 0; j < 8; ++j)
                    acc[i][j] = fmaf(a[i], bb[j], acc[i][j]);
        }
        __syncthreads();
    }

    float* Cp = C + (size_t)b * 256 * NPTS + n0;
    #pragma unroll
    for (int i = 0; i < 8; ++i) {
        int row = m0 + ty * 8 + i;
        float bv = bias[row];
        float4 o0 = make_float4(acc[i][0] + bv, acc[i][1] + bv,
                                acc[i][2] + bv, acc[i][3] + bv);
        float4 o1 = make_float4(acc[i][4] + bv, acc[i][5] + bv,
                                acc[i][6] + bv, acc[i][7] + bv);
        *(float4*)(Cp + (size_t)row * NPTS + tx * 8)     = o0;
        *(float4*)(Cp + (size_t)row * NPTS + tx * 8 + 4) = o1;
    }
}

__global__ void __launch_bounds__(256, 2)
gemm1_kernel(const float* __restrict__ W1, const float* __restrict__ b1) {
    gemm_body<CIN, false>(W1, g_Xbuf, b1, nullptr, nullptr, g_Y1);
}

__global__ void __launch_bounds__(256, 2)
gemm2_kernel(const float* __restrict__ W2, const float* __restrict__ b2,
             float* __restrict__ out) {
    gemm_body<CH, true>(W2, g_Y1, b2, g_scale1, g_shift1, out);
}

// ---------------- per-channel sum / sumsq reduction --------------------------
__device__ __forceinline__ void stats_body(const float* __restrict__ Y,
                                           float* __restrict__ gsum,
                                           float* __restrict__ gsq) {
    const int c = blockIdx.x, b = blockIdx.y;
    const float* p = Y + ((size_t)b * 256 + c) * NPTS;
    float s = 0.f, q = 0.f;
    for (int i = threadIdx.x * 4; i < NPTS; i += 256 * 4) {
        float4 v = *(const float4*)(p + i);
        s += v.x + v.y + v.z + v.w;
        q += v.x * v.x + v.y * v.y + v.z * v.z + v.w * v.w;
    }
    #pragma unroll
    for (int o = 16; o > 0; o >>= 1) {
        s += __shfl_down_sync(0xffffffffu, s, o);
        q += __shfl_down_sync(0xffffffffu, q, o);
    }
    __shared__ float ss[8], qq[8];
    int w = threadIdx.x >> 5;
    if ((threadIdx.x & 31) == 0) { ss[w] = s; qq[w] = q; }
    __syncthreads();
    if (threadIdx.x == 0) {
        float S = 0.f, Q = 0.f;
        #pragma unroll
        for (int i = 0; i < 8; ++i) { S += ss[i]; Q += qq[i]; }
        atomicAdd(&gsum[c], S);
        atomicAdd(&gsq[c], Q);
    }
}

__global__ void stats1_kernel() { stats_body(g_Y1, g_sum1, g_sumsq1); }
__global__ void stats2_kernel(const float* __restrict__ out) {
    stats_body(out, g_sum2, g_sumsq2);
}

// ---------------- finalize BN scale/shift ------------------------------------
__device__ __forceinline__ void finalize_body(const float* gsum, const float* gsq,
                                              const float* __restrict__ gamma,
                                              const float* __restrict__ beta,
                                              float* scale, float* shift) {
    const int c = threadIdx.x;
    const float inv = 1.0f / (float)((size_t)BATCH * NPTS);
    float m  = gsum[c] * inv;
    float v  = fmaxf(gsq[c] * inv - m * m, 0.f);
    float sc = gamma[c] * rsqrtf(v + BN_EPS);
    scale[c] = sc;
    shift[c] = beta[c] - m * sc;
}

__global__ void finalize1_kernel(const float* __restrict__ gamma,
                                 const float* __restrict__ beta) {
    finalize_body(g_sum1, g_sumsq1, gamma, beta, g_scale1, g_shift1);
}
__global__ void finalize2_kernel(const float* __restrict__ gamma,
                                 const float* __restrict__ beta) {
    finalize_body(g_sum2, g_sumsq2, gamma, beta, g_scale2, g_shift2);
}

// ---------------- final BN2 + ReLU, in place on d_out ------------------------
__global__ void apply2_kernel(float* __restrict__ out) {
    const int i4 = blockIdx.x * blockDim.x + threadIdx.x;  // float4 index
    const int c  = (i4 >> 10) & 255;                        // 1024 float4 per row
    float s = g_scale2[c], t = g_shift2[c];
    float4 v = ((float4*)out)[i4];
    v.x = fmaxf(fmaf(v.x, s, t), 0.f);
    v.y = fmaxf(fmaf(v.y, s, t), 0.f);
    v.z = fmaxf(fmaf(v.z, s, t), 0.f);
    v.w = fmaxf(fmaf(v.w, s, t), 0.f);
    ((float4*)out)[i4] = v;
}

// ---------------- launch ------------------------------------------------------
extern "C" void kernel_launch(void* const* d_in, const int* in_sizes, int n_in,
                              void* d_out, int out_size) {
    const float* feature1 = (const float*)d_in[0];
    const float* coord1   = (const float*)d_in[1];
    const float* feature2 = (const float*)d_in[2];
    const float* coord2   = (const float*)d_in[3];
    const float* W1 = (const float*)d_in[4];
    const float* b1 = (const float*)d_in[5];
    const float* gamma1 = (const float*)d_in[6];
    const float* beta1  = (const float*)d_in[7];
    const float* W2 = (const float*)d_in[8];
    const float* b2 = (const float*)d_in[9];
    const float* gamma2 = (const float*)d_in[10];
    const float* beta2  = (const float*)d_in[11];
    float* out = (float*)d_out;

    init_kernel<<<1, 256>>>();
    transpose_f2_kernel<<<dim3(GPTS / 32, D2 / 32, BATCH), dim3(32, 8)>>>(feature2);
    knn_interp_kernel<<<dim3(NPTS / 128, BATCH), 128>>>(coord1, coord2, feature1);

    gemm1_kernel<<<dim3(BATCH * NPTS / 128, 2), 256>>>(W1, b1);
    stats1_kernel<<<dim3(CH, BATCH), 256>>>();
    finalize1_kernel<<<1, CH>>>(gamma1, beta1);

    gemm2_kernel<<<dim3(BATCH * NPTS / 128, 2), 256>>>(W2, b2, out);
    stats2_kernel<<<dim3(COUT, BATCH), 256>>>(out);
    finalize2_kernel<<<1, COUT>>>(gamma2, beta2);

    apply2_kernel<<<(size_t)BATCH * COUT * NPTS / 4 / 256, 256>>>(out);
}

// round 5
// speedup vs baseline: 1.9928x; 1.9928x over previous
#include <cuda_runtime.h>
#include <cuda_bf16.h>
#include <math_constants.h>
#include <cstdint>

#define BATCH 16
#define NPTS  4096
#define GPTS  1024
#define D1    128
#define D2    256
#define CIN   384
#define CH    256
#define COUT  256
#define NT    (BATCH * NPTS)      /* 65536 flat rows */
#define BN_EPS 1e-5f

#define SROW 72                    /* smem row stride in bf16 (144 B) */

// ======================= scratch (device globals) ===========================
__device__ uint4 g_X1hi[(size_t)NT * CIN / 8];   // bf16 [NT][384]
__device__ uint4 g_X1lo[(size_t)NT * CIN / 8];
__device__ uint4 g_X2hi[(size_t)NT * CH / 8];    // bf16 [NT][256]
__device__ uint4 g_X2lo[(size_t)NT * CH / 8];
__device__ float g_Y1t[(size_t)NT * CH];          // fp32 [NT][256]
__device__ float g_Y2t[(size_t)NT * COUT];
__device__ float g_f2t[(size_t)BATCH * GPTS * D2];
__device__ uint4 g_W1hi[CH * CIN / 8], g_W1lo[CH * CIN / 8];     // bf16 [256][384]
__device__ uint4 g_W2hi[COUT * CH / 8], g_W2lo[COUT * CH / 8];   // bf16 [256][256]
__device__ float g_sum1[CH],   g_sumsq1[CH];
__device__ float g_sum2[COUT], g_sumsq2[COUT];
__device__ float g_scale1[CH],   g_shift1[CH];
__device__ float g_scale2[COUT], g_shift2[COUT];

// ======================= MMA helper =========================================
__device__ __forceinline__ void mma16816(float c[4],
                                         uint32_t a0, uint32_t a1, uint32_t a2, uint32_t a3,
                                         uint32_t b0, uint32_t b1) {
    asm volatile(
        "mma.sync.aligned.m16n8k16.row.col.f32.bf16.bf16.f32 "
        "{%0,%1,%2,%3}, {%4,%5,%6,%7}, {%8,%9}, {%0,%1,%2,%3};"
        : "+f"(c[0]), "+f"(c[1]), "+f"(c[2]), "+f"(c[3])
        : "r"(a0), "r"(a1), "r"(a2), "r"(a3), "r"(b0), "r"(b1));
}

// ======================= small kernels ======================================
__global__ void init_kernel() {
    int t = threadIdx.x;
    g_sum1[t] = 0.f; g_sumsq1[t] = 0.f;
    g_sum2[t] = 0.f; g_sumsq2[t] = 0.f;
}

__device__ __forceinline__ void split1(float v, __nv_bfloat16& h, __nv_bfloat16& l) {
    h = __float2bfloat16(v);
    l = __float2bfloat16(v - __bfloat162float(h));
}

__global__ void convert_w_kernel(const float* __restrict__ W1,
                                 const float* __restrict__ W2) {
    int i = blockIdx.x * blockDim.x + threadIdx.x;
    const int t1 = CH * CIN;
    const int t2 = COUT * CH;
    if (i < t1) {
        __nv_bfloat16 h, l; split1(W1[i], h, l);
        ((__nv_bfloat16*)g_W1hi)[i] = h;
        ((__nv_bfloat16*)g_W1lo)[i] = l;
    } else if (i < t1 + t2) {
        int j = i - t1;
        __nv_bfloat16 h, l; split1(W2[j], h, l);
        ((__nv_bfloat16*)g_W2hi)[j] = h;
        ((__nv_bfloat16*)g_W2lo)[j] = l;
    }
}

// transpose feature2: [B][D2][G] -> [B][G][D2]  (fp32)
__global__ void transpose_f2_kernel(const float* __restrict__ f2) {
    __shared__ float tile[32][33];
    int b  = blockIdx.z;
    int g0 = blockIdx.x * 32;
    int d0 = blockIdx.y * 32;
    const float* src = f2 + (size_t)b * D2 * GPTS;
    #pragma unroll
    for (int r = threadIdx.y; r < 32; r += 8)
        tile[r][threadIdx.x] = src[(size_t)(d0 + r) * GPTS + g0 + threadIdx.x];
    __syncthreads();
    float* dst = g_f2t + (size_t)b * GPTS * D2;
    #pragma unroll
    for (int r = threadIdx.y; r < 32; r += 8)
        dst[(size_t)(g0 + r) * D2 + d0 + threadIdx.x] = tile[threadIdx.x][r];
}

__device__ __forceinline__ void split8_store(const float v[8], uint4* hip, uint4* lop) {
    uint32_t h[4], l[4];
    #pragma unroll
    for (int i = 0; i < 4; ++i) {
        __nv_bfloat16 h0, l0, h1, l1;
        split1(v[2 * i], h0, l0);
        split1(v[2 * i + 1], h1, l1);
        h[i] = (uint32_t)__bfloat16_as_ushort(h0) | ((uint32_t)__bfloat16_as_ushort(h1) << 16);
        l[i] = (uint32_t)__bfloat16_as_ushort(l0) | ((uint32_t)__bfloat16_as_ushort(l1) << 16);
    }
    *hip = make_uint4(h[0], h[1], h[2], h[3]);
    *lop = make_uint4(l[0], l[1], l[2], l[3]);
}

// 3-NN + interp; writes bf16 hi/lo rows [flatrow][384]
__global__ void knn_interp_kernel(const float* __restrict__ coord1,
                                  const float* __restrict__ coord2,
                                  const float* __restrict__ feature1) {
    __shared__ float s2x[GPTS], s2y[GPTS], s2z[GPTS], s2n[GPTS];
    const int b = blockIdx.y;
    const int n = blockIdx.x * 128 + threadIdx.x;

    const float* c2 = coord2 + (size_t)b * 3 * GPTS;
    for (int g = threadIdx.x; g < GPTS; g += 128) {
        float x = c2[g], y = c2[GPTS + g], z = c2[2 * GPTS + g];
        s2x[g] = x; s2y[g] = y; s2z[g] = z;
        s2n[g] = x * x + y * y + z * z;
    }
    __syncthreads();

    const float* c1 = coord1 + (size_t)b * 3 * NPTS;
    const float x = c1[n], y = c1[NPTS + n], z = c1[2 * NPTS + n];
    const float q = x * x + y * y + z * z;

    float d0 = CUDART_INF_F, d1 = CUDART_INF_F, d2 = CUDART_INF_F;
    int   i0 = 0, i1 = 0, i2 = 0;
    #pragma unroll 4
    for (int g = 0; g < GPTS; ++g) {
        float dot  = x * s2x[g] + y * s2y[g] + z * s2z[g];
        float dist = q + s2n[g] - 2.0f * dot;
        if (dist < d2) {
            if (dist < d1) {
                d2 = d1; i2 = i1;
                if (dist < d0) { d1 = d0; i1 = i0; d0 = dist; i0 = g; }
                else           { d1 = dist; i1 = g; }
            } else { d2 = dist; i2 = g; }
        }
    }

    const float r0 = 1.0f / (d0 + 1e-8f);
    const float r1 = 1.0f / (d1 + 1e-8f);
    const float r2 = 1.0f / (d2 + 1e-8f);
    const float rs = 1.0f / (r0 + r1 + r2);
    const float w0 = r0 * rs, w1 = r1 * rs, w2 = r2 * rs;

    const size_t row = (size_t)b * NPTS + n;
    uint4* hip = g_X1hi + row * (CIN / 8);
    uint4* lop = g_X1lo + row * (CIN / 8);

    // feature1 -> channels [0,128)
    const float* f1 = feature1 + (size_t)b * D1 * NPTS + n;
    #pragma unroll 2
    for (int d8 = 0; d8 < D1 / 8; ++d8) {
        float v[8];
        #pragma unroll
        for (int j = 0; j < 8; ++j) v[j] = f1[(size_t)(d8 * 8 + j) * NPTS];
        split8_store(v, hip + d8, lop + d8);
    }

    // interp -> channels [128,384)
    const float* F = g_f2t + (size_t)b * GPTS * D2;
    const float4* p0 = (const float4*)(F + (size_t)i0 * D2);
    const float4* p1 = (const float4*)(F + (size_t)i1 * D2);
    const float4* p2 = (const float4*)(F + (size_t)i2 * D2);
    #pragma unroll 2
    for (int d8 = 0; d8 < D2 / 8; ++d8) {
        float4 a0 = p0[2 * d8], a1 = p0[2 * d8 + 1];
        float4 b0 = p1[2 * d8], b1 = p1[2 * d8 + 1];
        float4 e0 = p2[2 * d8], e1 = p2[2 * d8 + 1];
        float v[8];
        v[0] = w0 * a0.x + w1 * b0.x + w2 * e0.x;
        v[1] = w0 * a0.y + w1 * b0.y + w2 * e0.y;
        v[2] = w0 * a0.z + w1 * b0.z + w2 * e0.z;
        v[3] = w0 * a0.w + w1 * b0.w + w2 * e0.w;
        v[4] = w0 * a1.x + w1 * b1.x + w2 * e1.x;
        v[5] = w0 * a1.y + w1 * b1.y + w2 * e1.y;
        v[6] = w0 * a1.z + w1 * b1.z + w2 * e1.z;
        v[7] = w0 * a1.w + w1 * b1.w + w2 * e1.w;
        split8_store(v, hip + D1 / 8 + d8, lop + D1 / 8 + d8);
    }
}

// ======================= HMMA GEMM (explicit LDS fragments) =================
// C[m][n] = sum_k W[m][k] * X[n][k], split: Whi*Xhi + Whi*Xlo + Wlo*Xhi.
// CTA tile 128(M)x128(N), K-chunk 64. 8 warps = 2(M) x 4(N), warp tile 64x32.
// Output: Yt[n][m] fp32 + bias.
template <int LAYER>
__global__ void __launch_bounds__(256, 2)
gemm_mma_kernel(const float* __restrict__ bias) {
    constexpr int K0 = (LAYER == 1) ? CIN : CH;
    constexpr int KC = K0 / 64;

    const __nv_bfloat16* Whi = (LAYER == 1) ? (const __nv_bfloat16*)g_W1hi
                                            : (const __nv_bfloat16*)g_W2hi;
    const __nv_bfloat16* Wlo = (LAYER == 1) ? (const __nv_bfloat16*)g_W1lo
                                            : (const __nv_bfloat16*)g_W2lo;
    const __nv_bfloat16* Xhi = (LAYER == 1) ? (const __nv_bfloat16*)g_X1hi
                                            : (const __nv_bfloat16*)g_X2hi;
    const __nv_bfloat16* Xlo = (LAYER == 1) ? (const __nv_bfloat16*)g_X1lo
                                            : (const __nv_bfloat16*)g_X2lo;
    float* Yt = (LAYER == 1) ? g_Y1t : g_Y2t;

    __shared__ __align__(16) __nv_bfloat16 sA[128 * SROW];
    __shared__ __align__(16) __nv_bfloat16 sB[128 * SROW];

    const int tid  = threadIdx.x;
    const int wid  = tid >> 5, lane = tid & 31;
    const int tg   = lane >> 2;            // groupID (0..7)
    const int tig  = lane & 3;             // threadID_in_group (0..3)
    const size_t r0 = (size_t)blockIdx.x * 128;   // X row block
    const int m0 = blockIdx.y * 128;              // W row block
    const int wm = (wid & 1) * 64;
    const int wn = (wid >> 1) * 32;

    float acc[4][4][4];
    #pragma unroll
    for (int i = 0; i < 4; ++i)
        #pragma unroll
        for (int j = 0; j < 4; ++j)
            #pragma unroll
            for (int k = 0; k < 4; ++k) acc[i][j][k] = 0.f;

    for (int c = 0; c < 3 * KC; ++c) {
        const int phase = c / KC;
        const int kk = (c - phase * KC) * 64;
        const __nv_bfloat16* Asrc = (phase < 2) ? Whi : Wlo;
        const __nv_bfloat16* Bsrc = ((phase == 1) ? Xlo : Xhi);

        // load 128x64 bf16 tiles into padded smem (16B chunks)
        #pragma unroll
        for (int i = 0; i < 4; ++i) {
            int idx = tid + i * 256;           // 0..1023
            int r = idx >> 3, ch = idx & 7;
            *(uint4*)(&sA[r * SROW + ch * 8]) =
                *(const uint4*)(Asrc + (size_t)(m0 + r) * K0 + kk + ch * 8);
            *(uint4*)(&sB[r * SROW + ch * 8]) =
                *(const uint4*)(Bsrc + (r0 + r) * K0 + kk + ch * 8);
        }
        __syncthreads();

        #pragma unroll
        for (int ks = 0; ks < 4; ++ks) {      // k16 steps within 64-chunk
            const int kb = ks * 16;
            uint32_t b[4][2];
            #pragma unroll
            for (int ni = 0; ni < 4; ++ni) {
                const int rb = (wn + ni * 8 + tg) * SROW;
                b[ni][0] = *(const uint32_t*)(&sB[rb + kb + 2 * tig]);
                b[ni][1] = *(const uint32_t*)(&sB[rb + kb + 8 + 2 * tig]);
            }
            #pragma unroll
            for (int mi = 0; mi < 4; ++mi) {
                const int ra0 = (wm + mi * 16 + tg) * SROW;
                const int ra1 = ra0 + 8 * SROW;
                uint32_t a0 = *(const uint32_t*)(&sA[ra0 + kb + 2 * tig]);
                uint32_t a1 = *(const uint32_t*)(&sA[ra1 + kb + 2 * tig]);
                uint32_t a2 = *(const uint32_t*)(&sA[ra0 + kb + 8 + 2 * tig]);
                uint32_t a3 = *(const uint32_t*)(&sA[ra1 + kb + 8 + 2 * tig]);
                #pragma unroll
                for (int ni = 0; ni < 4; ++ni)
                    mma16816(acc[mi][ni], a0, a1, a2, a3, b[ni][0], b[ni][1]);
            }
        }
        __syncthreads();
    }

    // epilogue: Yt[(r0+n)*256 + m] = acc + bias[m]
    #pragma unroll
    for (int mi = 0; mi < 4; ++mi) {
        const int mg0 = m0 + wm + mi * 16 + tg;
        const int mg1 = mg0 + 8;
        const float bv0 = bias[mg0];
        const float bv1 = bias[mg1];
        #pragma unroll
        for (int ni = 0; ni < 4; ++ni) {
            const size_t n = r0 + wn + ni * 8 + 2 * tig;
            Yt[n * 256 + mg0]       = acc[mi][ni][0] + bv0;
            Yt[(n + 1) * 256 + mg0] = acc[mi][ni][1] + bv0;
            Yt[n * 256 + mg1]       = acc[mi][ni][2] + bv1;
            Yt[(n + 1) * 256 + mg1] = acc[mi][ni][3] + bv1;
        }
    }
}

// ======================= BN stats / finalize / fold =========================
// NOTE: globals referenced from DEVICE code only — passing __device__ symbols
// as host-side kernel arguments silently reads the host shadow on GB300 (ATS).
template <int LAYER>
__global__ void stats_kernel() {
    const float* Y = (LAYER == 1) ? g_Y1t : g_Y2t;
    float* gsum    = (LAYER == 1) ? g_sum1 : g_sum2;
    float* gsq     = (LAYER == 1) ? g_sumsq1 : g_sumsq2;
    const int c = threadIdx.x;
    const size_t r0 = (size_t)blockIdx.x * 256;
    const float* p = Y + r0 * 256 + c;
    float s = 0.f, q = 0.f;
    #pragma unroll 4
    for (int i = 0; i < 256; ++i) {
        float v = p[(size_t)i * 256];
        s += v; q += v * v;
    }
    atomicAdd(&gsum[c], s);
    atomicAdd(&gsq[c], q);
}

template <int LAYER>
__global__ void finalize_kernel(const float* __restrict__ gamma,
                                const float* __restrict__ beta) {
    const float* gsum = (LAYER == 1) ? g_sum1 : g_sum2;
    const float* gsq  = (LAYER == 1) ? g_sumsq1 : g_sumsq2;
    float* scale      = (LAYER == 1) ? g_scale1 : g_scale2;
    float* shift      = (LAYER == 1) ? g_shift1 : g_shift2;
    const int c = threadIdx.x;
    const float inv = 1.0f / (float)((size_t)NT);
    float m  = gsum[c] * inv;
    float v  = fmaxf(gsq[c] * inv - m * m, 0.f);
    float sc = gamma[c] * rsqrtf(v + BN_EPS);
    scale[c] = sc;
    shift[c] = beta[c] - m * sc;
}

// BN1 + ReLU + bf16 split: Y1t [row][256] -> X2hi/X2lo [row][256]
__global__ void convert2_kernel() {
    const int gid = blockIdx.x * 256 + threadIdx.x;       // one per 8 channels
    const size_t r = (size_t)(gid >> 5);
    const int c0 = (gid & 31) * 8;
    const float* p = g_Y1t + r * 256 + c0;
    float4 a = *(const float4*)(p);
    float4 b = *(const float4*)(p + 4);
    float4 s0 = *(const float4*)(g_scale1 + c0);
    float4 s1 = *(const float4*)(g_scale1 + c0 + 4);
    float4 t0 = *(const float4*)(g_shift1 + c0);
    float4 t1 = *(const float4*)(g_shift1 + c0 + 4);
    float v[8];
    v[0] = fmaxf(fmaf(a.x, s0.x, t0.x), 0.f);
    v[1] = fmaxf(fmaf(a.y, s0.y, t0.y), 0.f);
    v[2] = fmaxf(fmaf(a.z, s0.z, t0.z), 0.f);
    v[3] = fmaxf(fmaf(a.w, s0.w, t0.w), 0.f);
    v[4] = fmaxf(fmaf(b.x, s1.x, t1.x), 0.f);
    v[5] = fmaxf(fmaf(b.y, s1.y, t1.y), 0.f);
    v[6] = fmaxf(fmaf(b.z, s1.z, t1.z), 0.f);
    v[7] = fmaxf(fmaf(b.w, s1.w, t1.w), 0.f);
    split8_store(v, g_X2hi + (r * 256 + c0) / 8, g_X2lo + (r * 256 + c0) / 8);
}

// final: Y2t [row n][m] -> out [b][m][n] with BN2 + ReLU
__global__ void transpose_out_kernel(float* __restrict__ out) {
    __shared__ float tile[32][33];
    const int r0 = blockIdx.x * 32;     // flat row (b*N + n)
    const int c0 = blockIdx.y * 32;     // channel
    #pragma unroll
    for (int i = threadIdx.y; i < 32; i += 8)
        tile[i][threadIdx.x] = g_Y2t[(size_t)(r0 + i) * 256 + c0 + threadIdx.x];
    __syncthreads();
    const int b  = r0 >> 12;
    const int n0 = r0 & (NPTS - 1);
    #pragma unroll
    for (int i = threadIdx.y; i < 32; i += 8) {
        int c = c0 + i;
        float s = g_scale2[c], t = g_shift2[c];
        out[((size_t)b * 256 + c) * NPTS + n0 + threadIdx.x] =
            fmaxf(fmaf(tile[threadIdx.x][i], s, t), 0.f);
    }
}

// ======================= launch =============================================
extern "C" void kernel_launch(void* const* d_in, const int* in_sizes, int n_in,
                              void* d_out, int out_size) {
    const float* feature1 = (const float*)d_in[0];
    const float* coord1   = (const float*)d_in[1];
    const float* feature2 = (const float*)d_in[2];
    const float* coord2   = (const float*)d_in[3];
    const float* W1 = (const float*)d_in[4];
    const float* b1 = (const float*)d_in[5];
    const float* gamma1 = (const float*)d_in[6];
    const float* beta1  = (const float*)d_in[7];
    const float* W2 = (const float*)d_in[8];
    const float* b2 = (const float*)d_in[9];
    const float* gamma2 = (const float*)d_in[10];
    const float* beta2  = (const float*)d_in[11];
    float* out = (float*)d_out;

    init_kernel<<<1, 256>>>();
    convert_w_kernel<<<(CH * CIN + COUT * CH + 255) / 256, 256>>>(W1, W2);
    transpose_f2_kernel<<<dim3(GPTS / 32, D2 / 32, BATCH), dim3(32, 8)>>>(feature2);
    knn_interp_kernel<<<dim3(NPTS / 128, BATCH), 128>>>(coord1, coord2, feature1);

    gemm_mma_kernel<1><<<dim3(NT / 128, 2), 256>>>(b1);
    stats_kernel<1><<<NT / 256, 256>>>();
    finalize_kernel<1><<<1, CH>>>(gamma1, beta1);
    convert2_kernel<<<NT * 32 / 256, 256>>>();

    gemm_mma_kernel<2><<<dim3(NT / 128, 2), 256>>>(b2);
    stats_kernel<2><<<NT / 256, 256>>>();
    finalize_kernel<2><<<1, COUT>>>(gamma2, beta2);

    transpose_out_kernel<<<dim3(NT / 32, 256 / 32), dim3(32, 8)>>>(out);
}

// round 6
// speedup vs baseline: 2.5406x; 1.2749x over previous
#include <cuda_runtime.h>
#include <cuda_bf16.h>
#include <math_constants.h>
#include <cstdint>

#define BATCH 16
#define NPTS  4096
#define GPTS  1024
#define D1    128
#define D2    256
#define CIN   384
#define CH    256
#define COUT  256
#define NT    (BATCH * NPTS)      /* 65536 flat rows */
#define BN_EPS 1e-5f

#define SROW 72                    /* smem row stride in bf16 (144 B) */
#define TILEB (128 * SROW * 2)     /* one tile stage in bytes */

// ======================= scratch (device globals) ===========================
__device__ uint4 g_X1hi[(size_t)NT * CIN / 8];   // bf16 [NT][384]
__device__ uint4 g_X1lo[(size_t)NT * CIN / 8];
__device__ uint4 g_X2hi[(size_t)NT * CH / 8];    // bf16 [NT][256]
__device__ uint4 g_X2lo[(size_t)NT * CH / 8];
__device__ float g_Y1t[(size_t)NT * CH];          // fp32 [NT][256]
__device__ float g_Y2t[(size_t)NT * COUT];
__device__ float g_f2t[(size_t)BATCH * GPTS * D2];
__device__ uint4 g_W1hi[CH * CIN / 8], g_W1lo[CH * CIN / 8];     // bf16 [256][384]
__device__ uint4 g_W2hi[COUT * CH / 8], g_W2lo[COUT * CH / 8];   // bf16 [256][256]
__device__ float g_sum1[CH],   g_sumsq1[CH];
__device__ float g_sum2[COUT], g_sumsq2[COUT];
__device__ float g_scale1[CH],   g_shift1[CH];
__device__ float g_scale2[COUT], g_shift2[COUT];

// ======================= asm helpers ========================================
__device__ __forceinline__ uint32_t smem_u32(const void* p) {
    uint32_t a;
    asm("{ .reg .u64 t; cvta.to.shared.u64 t, %1; cvt.u32.u64 %0, t; }"
        : "=r"(a) : "l"(p));
    return a;
}

#define CPA16(dst_u32, src_ptr) \
    asm volatile("cp.async.cg.shared.global [%0], [%1], 16;" \
                 :: "r"(dst_u32), "l"(src_ptr) : "memory")
#define CP_COMMIT() asm volatile("cp.async.commit_group;" ::: "memory")
#define CP_WAIT1()  asm volatile("cp.async.wait_group 1;" ::: "memory")
#define CP_WAIT0()  asm volatile("cp.async.wait_group 0;" ::: "memory")

__device__ __forceinline__ void mma16816(float c[4],
                                         uint32_t a0, uint32_t a1, uint32_t a2, uint32_t a3,
                                         uint32_t b0, uint32_t b1) {
    asm volatile(
        "mma.sync.aligned.m16n8k16.row.col.f32.bf16.bf16.f32 "
        "{%0,%1,%2,%3}, {%4,%5,%6,%7}, {%8,%9}, {%0,%1,%2,%3};"
        : "+f"(c[0]), "+f"(c[1]), "+f"(c[2]), "+f"(c[3])
        : "r"(a0), "r"(a1), "r"(a2), "r"(a3), "r"(b0), "r"(b1));
}

// ======================= small kernels ======================================
__global__ void init_kernel() {
    int t = threadIdx.x;
    g_sum1[t] = 0.f; g_sumsq1[t] = 0.f;
    g_sum2[t] = 0.f; g_sumsq2[t] = 0.f;
}

__device__ __forceinline__ void split1(float v, __nv_bfloat16& h, __nv_bfloat16& l) {
    h = __float2bfloat16(v);
    l = __float2bfloat16(v - __bfloat162float(h));
}

__global__ void convert_w_kernel(const float* __restrict__ W1,
                                 const float* __restrict__ W2) {
    int i = blockIdx.x * blockDim.x + threadIdx.x;
    const int t1 = CH * CIN;
    const int t2 = COUT * CH;
    if (i < t1) {
        __nv_bfloat16 h, l; split1(W1[i], h, l);
        ((__nv_bfloat16*)g_W1hi)[i] = h;
        ((__nv_bfloat16*)g_W1lo)[i] = l;
    } else if (i < t1 + t2) {
        int j = i - t1;
        __nv_bfloat16 h, l; split1(W2[j], h, l);
        ((__nv_bfloat16*)g_W2hi)[j] = h;
        ((__nv_bfloat16*)g_W2lo)[j] = l;
    }
}

// transpose feature2: [B][D2][G] -> [B][G][D2]  (fp32)
__global__ void transpose_f2_kernel(const float* __restrict__ f2) {
    __shared__ float tile[32][33];
    int b  = blockIdx.z;
    int g0 = blockIdx.x * 32;
    int d0 = blockIdx.y * 32;
    const float* src = f2 + (size_t)b * D2 * GPTS;
    #pragma unroll
    for (int r = threadIdx.y; r < 32; r += 8)
        tile[r][threadIdx.x] = src[(size_t)(d0 + r) * GPTS + g0 + threadIdx.x];
    __syncthreads();
    float* dst = g_f2t + (size_t)b * GPTS * D2;
    #pragma unroll
    for (int r = threadIdx.y; r < 32; r += 8)
        dst[(size_t)(g0 + r) * D2 + d0 + threadIdx.x] = tile[threadIdx.x][r];
}

__device__ __forceinline__ void split8_store(const float v[8], uint4* hip, uint4* lop) {
    uint32_t h[4], l[4];
    #pragma unroll
    for (int i = 0; i < 4; ++i) {
        __nv_bfloat16 h0, l0, h1, l1;
        split1(v[2 * i], h0, l0);
        split1(v[2 * i + 1], h1, l1);
        h[i] = (uint32_t)__bfloat16_as_ushort(h0) | ((uint32_t)__bfloat16_as_ushort(h1) << 16);
        l[i] = (uint32_t)__bfloat16_as_ushort(l0) | ((uint32_t)__bfloat16_as_ushort(l1) << 16);
    }
    *hip = make_uint4(h[0], h[1], h[2], h[3]);
    *lop = make_uint4(l[0], l[1], l[2], l[3]);
}

// 3-NN + interp, 4 lanes per query point. Block 256 = 64 points x 4 lanes.
__global__ void knn_interp_kernel(const float* __restrict__ coord1,
                                  const float* __restrict__ coord2,
                                  const float* __restrict__ feature1) {
    __shared__ float s2x[GPTS], s2y[GPTS], s2z[GPTS], s2n[GPTS];
    const int b   = blockIdx.y;
    const int tid = threadIdx.x;
    const int q   = tid & 3;                        // lane within point group
    const int n   = blockIdx.x * 64 + (tid >> 2);   // query point

    const float* c2 = coord2 + (size_t)b * 3 * GPTS;
    for (int g = tid; g < GPTS; g += 256) {
        float x = c2[g], y = c2[GPTS + g], z = c2[2 * GPTS + g];
        s2x[g] = x; s2y[g] = y; s2z[g] = z;
        s2n[g] = x * x + y * y + z * z;
    }
    __syncthreads();

    const float* c1 = coord1 + (size_t)b * 3 * NPTS;
    const float x = c1[n], y = c1[NPTS + n], z = c1[2 * NPTS + n];
    const float qn = x * x + y * y + z * z;

    float d0 = CUDART_INF_F, d1 = CUDART_INF_F, d2 = CUDART_INF_F;
    int   i0 = 0, i1 = 0, i2 = 0;
    #pragma unroll 4
    for (int it = 0; it < GPTS / 4; ++it) {
        const int g = q + it * 4;
        float dot  = x * s2x[g] + y * s2y[g] + z * s2z[g];
        float dist = qn + s2n[g] - 2.0f * dot;
        if (dist < d2) {
            if (dist < d1) {
                d2 = d1; i2 = i1;
                if (dist < d0) { d1 = d0; i1 = i0; d0 = dist; i0 = g; }
                else           { d1 = dist; i1 = g; }
            } else { d2 = dist; i2 = g; }
        }
    }

    // butterfly merge of sorted top-3 lists across the 4 lanes
    #pragma unroll
    for (int off = 1; off <= 2; off <<= 1) {
        float e0 = __shfl_xor_sync(0xffffffffu, d0, off);
        float e1 = __shfl_xor_sync(0xffffffffu, d1, off);
        float e2 = __shfl_xor_sync(0xffffffffu, d2, off);
        int   j0 = __shfl_xor_sync(0xffffffffu, i0, off);
        int   j1 = __shfl_xor_sync(0xffffffffu, i1, off);
        int   j2 = __shfl_xor_sync(0xffffffffu, i2, off);
        float f0, f1, f2; int k0, k1, k2;
        if (d0 <= e0) {
            f0 = d0; k0 = i0;
            if (d1 <= e0) {
                f1 = d1; k1 = i1;
                if (d2 <= e0) { f2 = d2; k2 = i2; } else { f2 = e0; k2 = j0; }
            } else {
                f1 = e0; k1 = j0;
                if (d1 <= e1) { f2 = d1; k2 = i1; } else { f2 = e1; k2 = j1; }
            }
        } else {
            f0 = e0; k0 = j0;
            if (e1 <= d0) {
                f1 = e1; k1 = j1;
                if (e2 <= d0) { f2 = e2; k2 = j2; } else { f2 = d0; k2 = i0; }
            } else {
                f1 = d0; k1 = i0;
                if (e1 <= d1) { f2 = e1; k2 = j1; } else { f2 = d1; k2 = i1; }
            }
        }
        d0 = f0; i0 = k0; d1 = f1; i1 = k1; d2 = f2; i2 = k2;
    }

    const float r0w = 1.0f / (d0 + 1e-8f);
    const float r1w = 1.0f / (d1 + 1e-8f);
    const float r2w = 1.0f / (d2 + 1e-8f);
    const float rs = 1.0f / (r0w + r1w + r2w);
    const float w0 = r0w * rs, w1 = r1w * rs, w2 = r2w * rs;

    const size_t row = (size_t)b * NPTS + n;
    uint4* hip = g_X1hi + row * (CIN / 8);
    uint4* lop = g_X1lo + row * (CIN / 8);

    // feature1 -> channels [0,128): lane q handles chunks q*4 .. q*4+3
    const float* f1 = feature1 + (size_t)b * D1 * NPTS + n;
    #pragma unroll
    for (int d8 = q * 4; d8 < q * 4 + 4; ++d8) {
        float v[8];
        #pragma unroll
        for (int j = 0; j < 8; ++j) v[j] = f1[(size_t)(d8 * 8 + j) * NPTS];
        split8_store(v, hip + d8, lop + d8);
    }

    // interp -> channels [128,384): lane q handles chunks q*8 .. q*8+7
    const float* F = g_f2t + (size_t)b * GPTS * D2;
    const float4* p0 = (const float4*)(F + (size_t)i0 * D2);
    const float4* p1 = (const float4*)(F + (size_t)i1 * D2);
    const float4* p2 = (const float4*)(F + (size_t)i2 * D2);
    #pragma unroll
    for (int d8 = q * 8; d8 < q * 8 + 8; ++d8) {
        float4 a0 = p0[2 * d8], a1 = p0[2 * d8 + 1];
        float4 b0 = p1[2 * d8], b1 = p1[2 * d8 + 1];
        float4 e0 = p2[2 * d8], e1 = p2[2 * d8 + 1];
        float v[8];
        v[0] = w0 * a0.x + w1 * b0.x + w2 * e0.x;
        v[1] = w0 * a0.y + w1 * b0.y + w2 * e0.y;
        v[2] = w0 * a0.z + w1 * b0.z + w2 * e0.z;
        v[3] = w0 * a0.w + w1 * b0.w + w2 * e0.w;
        v[4] = w0 * a1.x + w1 * b1.x + w2 * e1.x;
        v[5] = w0 * a1.y + w1 * b1.y + w2 * e1.y;
        v[6] = w0 * a1.z + w1 * b1.z + w2 * e1.z;
        v[7] = w0 * a1.w + w1 * b1.w + w2 * e1.w;
        split8_store(v, hip + D1 / 8 + d8, lop + D1 / 8 + d8);
    }
}

// ======================= HMMA GEMM (cp.async double-buffered) ===============
// C[m][n] = sum_k W[m][k] * X[n][k], split: Whi*Xhi + Whi*Xlo + Wlo*Xhi.
// CTA tile 128(M)x128(N), K-chunk 64, 2-stage pipeline. 8 warps = 2(M)x4(N).
// Epilogue: Yt[n][m] = acc + bias[m]; BN stats (sum/sumsq) fused via RED.
template <int LAYER>
__global__ void __launch_bounds__(256, 2)
gemm_mma_kernel(const float* __restrict__ bias) {
    constexpr int K0 = (LAYER == 1) ? CIN : CH;
    constexpr int KC = K0 / 64;
    constexpr int NC = 3 * KC;

    const __nv_bfloat16* Whi = (LAYER == 1) ? (const __nv_bfloat16*)g_W1hi
                                            : (const __nv_bfloat16*)g_W2hi;
    const __nv_bfloat16* Wlo = (LAYER == 1) ? (const __nv_bfloat16*)g_W1lo
                                            : (const __nv_bfloat16*)g_W2lo;
    const __nv_bfloat16* Xhi = (LAYER == 1) ? (const __nv_bfloat16*)g_X1hi
                                            : (const __nv_bfloat16*)g_X2hi;
    const __nv_bfloat16* Xlo = (LAYER == 1) ? (const __nv_bfloat16*)g_X1lo
                                            : (const __nv_bfloat16*)g_X2lo;
    float* Yt    = (LAYER == 1) ? g_Y1t : g_Y2t;
    float* gsum  = (LAYER == 1) ? g_sum1 : g_sum2;
    float* gsq   = (LAYER == 1) ? g_sumsq1 : g_sumsq2;

    __shared__ __align__(16) __nv_bfloat16 sA[2][128 * SROW];
    __shared__ __align__(16) __nv_bfloat16 sB[2][128 * SROW];

    const int tid  = threadIdx.x;
    const int wid  = tid >> 5, lane = tid & 31;
    const int tg   = lane >> 2;            // groupID (0..7)
    const int tig  = lane & 3;             // threadID_in_group (0..3)
    const size_t r0 = (size_t)blockIdx.x * 128;   // X row block
    const int m0 = blockIdx.y * 128;              // W row block
    const int wm = (wid & 1) * 64;
    const int wn = (wid >> 1) * 32;

    const uint32_t saA = smem_u32(sA);
    const uint32_t saB = smem_u32(sB);
    const int ldr  = tid >> 3;             // load row (0..31 step per iter)
    const int ldch = tid & 7;              // 16B chunk in row
    const uint32_t ldoff = (uint32_t)(ldr * SROW + ldch * 8) * 2;

    float acc[4][4][4];
    #pragma unroll
    for (int i = 0; i < 4; ++i)
        #pragma unroll
        for (int j = 0; j < 4; ++j)
            #pragma unroll
            for (int k = 0; k < 4; ++k) acc[i][j][k] = 0.f;

    // ---- issue loads for chunk c into stage st ----
    auto issue = [&](int c, int st) {
        const int phase = c / KC;
        const int kk = (c - phase * KC) * 64;
        const __nv_bfloat16* Asrc = (phase < 2) ? Whi : Wlo;
        const __nv_bfloat16* Bsrc = ((phase == 1) ? Xlo : Xhi);
        const uint32_t baseA = saA + (uint32_t)st * TILEB + ldoff;
        const uint32_t baseB = saB + (uint32_t)st * TILEB + ldoff;
        #pragma unroll
        for (int i = 0; i < 4; ++i) {
            const int r = ldr + i * 32;
            CPA16(baseA + (uint32_t)(i * 32 * SROW * 2),
                  Asrc + (size_t)(m0 + r) * K0 + kk + ldch * 8);
            CPA16(baseB + (uint32_t)(i * 32 * SROW * 2),
                  Bsrc + (r0 + r) * K0 + kk + ldch * 8);
        }
        CP_COMMIT();
    };

    issue(0, 0);
    for (int c = 0; c < NC; ++c) {
        const int st = c & 1;
        if (c + 1 < NC) { issue(c + 1, st ^ 1); CP_WAIT1(); }
        else            { CP_WAIT0(); }
        __syncthreads();

        const __nv_bfloat16* A = sA[st];
        const __nv_bfloat16* B = sB[st];
        #pragma unroll
        for (int ks = 0; ks < 4; ++ks) {      // k16 steps within 64-chunk
            const int kb = ks * 16;
            uint32_t b[4][2];
            #pragma unroll
            for (int ni = 0; ni < 4; ++ni) {
                const int rb = (wn + ni * 8 + tg) * SROW;
                b[ni][0] = *(const uint32_t*)(&B[rb + kb + 2 * tig]);
                b[ni][1] = *(const uint32_t*)(&B[rb + kb + 8 + 2 * tig]);
            }
            #pragma unroll
            for (int mi = 0; mi < 4; ++mi) {
                const int ra0 = (wm + mi * 16 + tg) * SROW;
                const int ra1 = ra0 + 8 * SROW;
                uint32_t a0 = *(const uint32_t*)(&A[ra0 + kb + 2 * tig]);
                uint32_t a1 = *(const uint32_t*)(&A[ra1 + kb + 2 * tig]);
                uint32_t a2 = *(const uint32_t*)(&A[ra0 + kb + 8 + 2 * tig]);
                uint32_t a3 = *(const uint32_t*)(&A[ra1 + kb + 8 + 2 * tig]);
                #pragma unroll
                for (int ni = 0; ni < 4; ++ni)
                    mma16816(acc[mi][ni], a0, a1, a2, a3, b[ni][0], b[ni][1]);
            }
        }
        __syncthreads();
    }

    // epilogue: store + fused BN stats
    #pragma unroll
    for (int mi = 0; mi < 4; ++mi) {
        const int mg0 = m0 + wm + mi * 16 + tg;
        const int mg1 = mg0 + 8;
        const float bv0 = bias[mg0];
        const float bv1 = bias[mg1];
        float s0 = 0.f, q0 = 0.f, s1 = 0.f, q1 = 0.f;
        #pragma unroll
        for (int ni = 0; ni < 4; ++ni) {
            const size_t n = r0 + wn + ni * 8 + 2 * tig;
            const float v00 = acc[mi][ni][0] + bv0;
            const float v01 = acc[mi][ni][1] + bv0;
            const float v10 = acc[mi][ni][2] + bv1;
            const float v11 = acc[mi][ni][3] + bv1;
            Yt[n * 256 + mg0]       = v00;
            Yt[(n + 1) * 256 + mg0] = v01;
            Yt[n * 256 + mg1]       = v10;
            Yt[(n + 1) * 256 + mg1] = v11;
            s0 += v00 + v01; q0 += v00 * v00 + v01 * v01;
            s1 += v10 + v11; q1 += v10 * v10 + v11 * v11;
        }
        // reduce over the 4 tig lanes (xor on low 2 bits of lane)
        #pragma unroll
        for (int off = 1; off <= 2; off <<= 1) {
            s0 += __shfl_xor_sync(0xffffffffu, s0, off);
            q0 += __shfl_xor_sync(0xffffffffu, q0, off);
            s1 += __shfl_xor_sync(0xffffffffu, s1, off);
            q1 += __shfl_xor_sync(0xffffffffu, q1, off);
        }
        if (tig == 0) {
            atomicAdd(&gsum[mg0], s0); atomicAdd(&gsq[mg0], q0);
            atomicAdd(&gsum[mg1], s1); atomicAdd(&gsq[mg1], q1);
        }
    }
}

// ======================= finalize / fold ====================================
template <int LAYER>
__global__ void finalize_kernel(const float* __restrict__ gamma,
                                const float* __restrict__ beta) {
    const float* gsum = (LAYER == 1) ? g_sum1 : g_sum2;
    const float* gsq  = (LAYER == 1) ? g_sumsq1 : g_sumsq2;
    float* scale      = (LAYER == 1) ? g_scale1 : g_scale2;
    float* shift      = (LAYER == 1) ? g_shift1 : g_shift2;
    const int c = threadIdx.x;
    const float inv = 1.0f / (float)((size_t)NT);
    float m  = gsum[c] * inv;
    float v  = fmaxf(gsq[c] * inv - m * m, 0.f);
    float sc = gamma[c] * rsqrtf(v + BN_EPS);
    scale[c] = sc;
    shift[c] = beta[c] - m * sc;
}

// BN1 + ReLU + bf16 split: Y1t [row][256] -> X2hi/X2lo [row][256]
__global__ void convert2_kernel() {
    const int gid = blockIdx.x * 256 + threadIdx.x;       // one per 8 channels
    const size_t r = (size_t)(gid >> 5);
    const int c0 = (gid & 31) * 8;
    const float* p = g_Y1t + r * 256 + c0;
    float4 a = *(const float4*)(p);
    float4 b = *(const float4*)(p + 4);
    float4 s0 = *(const float4*)(g_scale1 + c0);
    float4 s1 = *(const float4*)(g_scale1 + c0 + 4);
    float4 t0 = *(const float4*)(g_shift1 + c0);
    float4 t1 = *(const float4*)(g_shift1 + c0 + 4);
    float v[8];
    v[0] = fmaxf(fmaf(a.x, s0.x, t0.x), 0.f);
    v[1] = fmaxf(fmaf(a.y, s0.y, t0.y), 0.f);
    v[2] = fmaxf(fmaf(a.z, s0.z, t0.z), 0.f);
    v[3] = fmaxf(fmaf(a.w, s0.w, t0.w), 0.f);
    v[4] = fmaxf(fmaf(b.x, s1.x, t1.x), 0.f);
    v[5] = fmaxf(fmaf(b.y, s1.y, t1.y), 0.f);
    v[6] = fmaxf(fmaf(b.z, s1.z, t1.z), 0.f);
    v[7] = fmaxf(fmaf(b.w, s1.w, t1.w), 0.f);
    split8_store(v, g_X2hi + (r * 256 + c0) / 8, g_X2lo + (r * 256 + c0) / 8);
}

// final: Y2t [row n][m] -> out [b][m][n] with BN2 + ReLU
__global__ void transpose_out_kernel(float* __restrict__ out) {
    __shared__ float tile[32][33];
    const int r0 = blockIdx.x * 32;     // flat row (b*N + n)
    const int c0 = blockIdx.y * 32;     // channel
    #pragma unroll
    for (int i = threadIdx.y; i < 32; i += 8)
        tile[i][threadIdx.x] = g_Y2t[(size_t)(r0 + i) * 256 + c0 + threadIdx.x];
    __syncthreads();
    const int b  = r0 >> 12;
    const int n0 = r0 & (NPTS - 1);
    #pragma unroll
    for (int i = threadIdx.y; i < 32; i += 8) {
        int c = c0 + i;
        float s = g_scale2[c], t = g_shift2[c];
        out[((size_t)b * 256 + c) * NPTS + n0 + threadIdx.x] =
            fmaxf(fmaf(tile[threadIdx.x][i], s, t), 0.f);
    }
}

// ======================= launch =============================================
extern "C" void kernel_launch(void* const* d_in, const int* in_sizes, int n_in,
                              void* d_out, int out_size) {
    const float* feature1 = (const float*)d_in[0];
    const float* coord1   = (const float*)d_in[1];
    const float* feature2 = (const float*)d_in[2];
    const float* coord2   = (const float*)d_in[3];
    const float* W1 = (const float*)d_in[4];
    const float* b1 = (const float*)d_in[5];
    const float* gamma1 = (const float*)d_in[6];
    const float* beta1  = (const float*)d_in[7];
    const float* W2 = (const float*)d_in[8];
    const float* b2 = (const float*)d_in[9];
    const float* gamma2 = (const float*)d_in[10];
    const float* beta2  = (const float*)d_in[11];
    float* out = (float*)d_out;

    init_kernel<<<1, 256>>>();
    convert_w_kernel<<<(CH * CIN + COUT * CH + 255) / 256, 256>>>(W1, W2);
    transpose_f2_kernel<<<dim3(GPTS / 32, D2 / 32, BATCH), dim3(32, 8)>>>(feature2);
    knn_interp_kernel<<<dim3(NPTS / 64, BATCH), 256>>>(coord1, coord2, feature1);

    gemm_mma_kernel<1><<<dim3(NT / 128, 2), 256>>>(b1);
    finalize_kernel<1><<<1, CH>>>(gamma1, beta1);
    convert2_kernel<<<NT * 32 / 256, 256>>>();

    gemm_mma_kernel<2><<<dim3(NT / 128, 2), 256>>>(b2);
    finalize_kernel<2><<<1, COUT>>>(gamma2, beta2);

    transpose_out_kernel<<<dim3(NT / 32, 256 / 32), dim3(32, 8)>>>(out);
}

// round 7
// speedup vs baseline: 2.6300x; 1.0352x over previous
#include <cuda_runtime.h>
#include <cuda_bf16.h>
#include <math_constants.h>
#include <cstdint>

#define BATCH 16
#define NPTS  4096
#define GPTS  1024
#define D1    128
#define D2    256
#define CIN   384
#define CH    256
#define COUT  256
#define NT    (BATCH * NPTS)      /* 65536 flat rows */
#define BN_EPS 1e-5f

#define SROW 72                    /* smem row stride in bf16 (144 B) */
#define TILEB (128 * SROW * 2)     /* one tile stage in bytes */

// ======================= scratch (device globals) ===========================
__device__ uint4 g_X1hi[(size_t)NT * CIN / 8];   // bf16 [NT][384]
__device__ uint4 g_X1lo[(size_t)NT * CIN / 8];
__device__ uint4 g_X2hi[(size_t)NT * CH / 8];    // bf16 [NT][256]
__device__ uint4 g_X2lo[(size_t)NT * CH / 8];
__device__ float g_Y1t[(size_t)NT * CH];          // fp32 [NT][256]
__device__ float g_Y2t[(size_t)NT * COUT];
__device__ float g_f2t[(size_t)BATCH * GPTS * D2];
__device__ uint4 g_W1hi[CH * CIN / 8], g_W1lo[CH * CIN / 8];     // bf16 [256][384]
__device__ uint4 g_W2hi[COUT * CH / 8], g_W2lo[COUT * CH / 8];   // bf16 [256][256]
__device__ float g_sum1[CH],   g_sumsq1[CH];
__device__ float g_sum2[COUT], g_sumsq2[COUT];
__device__ float g_scale1[CH],   g_shift1[CH];
__device__ float g_scale2[COUT], g_shift2[COUT];

// ======================= asm helpers ========================================
__device__ __forceinline__ uint32_t smem_u32(const void* p) {
    uint32_t a;
    asm("{ .reg .u64 t; cvta.to.shared.u64 t, %1; cvt.u32.u64 %0, t; }"
        : "=r"(a) : "l"(p));
    return a;
}

#define CPA16(dst_u32, src_ptr) \
    asm volatile("cp.async.cg.shared.global [%0], [%1], 16;" \
                 :: "r"(dst_u32), "l"(src_ptr) : "memory")
#define CP_COMMIT() asm volatile("cp.async.commit_group;" ::: "memory")
#define CP_WAIT1()  asm volatile("cp.async.wait_group 1;" ::: "memory")
#define CP_WAIT0()  asm volatile("cp.async.wait_group 0;" ::: "memory")

__device__ __forceinline__ void mma16816(float c[4],
                                         uint32_t a0, uint32_t a1, uint32_t a2, uint32_t a3,
                                         uint32_t b0, uint32_t b1) {
    asm volatile(
        "mma.sync.aligned.m16n8k16.row.col.f32.bf16.bf16.f32 "
        "{%0,%1,%2,%3}, {%4,%5,%6,%7}, {%8,%9}, {%0,%1,%2,%3};"
        : "+f"(c[0]), "+f"(c[1]), "+f"(c[2]), "+f"(c[3])
        : "r"(a0), "r"(a1), "r"(a2), "r"(a3), "r"(b0), "r"(b1));
}

// ======================= small kernels ======================================
__global__ void init_kernel() {
    int t = threadIdx.x;
    g_sum1[t] = 0.f; g_sumsq1[t] = 0.f;
    g_sum2[t] = 0.f; g_sumsq2[t] = 0.f;
}

__device__ __forceinline__ void split1(float v, __nv_bfloat16& h, __nv_bfloat16& l) {
    h = __float2bfloat16(v);
    l = __float2bfloat16(v - __bfloat162float(h));
}

__global__ void convert_w_kernel(const float* __restrict__ W1,
                                 const float* __restrict__ W2) {
    int i = blockIdx.x * blockDim.x + threadIdx.x;
    const int t1 = CH * CIN;
    const int t2 = COUT * CH;
    if (i < t1) {
        __nv_bfloat16 h, l; split1(W1[i], h, l);
        ((__nv_bfloat16*)g_W1hi)[i] = h;
        ((__nv_bfloat16*)g_W1lo)[i] = l;
    } else if (i < t1 + t2) {
        int j = i - t1;
        __nv_bfloat16 h, l; split1(W2[j], h, l);
        ((__nv_bfloat16*)g_W2hi)[j] = h;
        ((__nv_bfloat16*)g_W2lo)[j] = l;
    }
}

// transpose feature2: [B][D2][G] -> [B][G][D2]  (fp32)
__global__ void transpose_f2_kernel(const float* __restrict__ f2) {
    __shared__ float tile[32][33];
    int b  = blockIdx.z;
    int g0 = blockIdx.x * 32;
    int d0 = blockIdx.y * 32;
    const float* src = f2 + (size_t)b * D2 * GPTS;
    #pragma unroll
    for (int r = threadIdx.y; r < 32; r += 8)
        tile[r][threadIdx.x] = src[(size_t)(d0 + r) * GPTS + g0 + threadIdx.x];
    __syncthreads();
    float* dst = g_f2t + (size_t)b * GPTS * D2;
    #pragma unroll
    for (int r = threadIdx.y; r < 32; r += 8)
        dst[(size_t)(g0 + r) * D2 + d0 + threadIdx.x] = tile[threadIdx.x][r];
}

__device__ __forceinline__ void split8_store(const float v[8], uint4* hip, uint4* lop) {
    uint32_t h[4], l[4];
    #pragma unroll
    for (int i = 0; i < 4; ++i) {
        __nv_bfloat16 h0, l0, h1, l1;
        split1(v[2 * i], h0, l0);
        split1(v[2 * i + 1], h1, l1);
        h[i] = (uint32_t)__bfloat16_as_ushort(h0) | ((uint32_t)__bfloat16_as_ushort(h1) << 16);
        l[i] = (uint32_t)__bfloat16_as_ushort(l0) | ((uint32_t)__bfloat16_as_ushort(l1) << 16);
    }
    *hip = make_uint4(h[0], h[1], h[2], h[3]);
    *lop = make_uint4(l[0], l[1], l[2], l[3]);
}

// 3-NN + interp, 8 lanes per query point. Block 256 = 32 points x 8 lanes.
// Candidate smem packed as float4 (x, y, z, -0.5*|c|^2); rank by
// e = dot - 0.5|c|^2 (maximize), recover dist = qn - 2e at the end.
__global__ void knn_interp_kernel(const float* __restrict__ coord1,
                                  const float* __restrict__ coord2,
                                  const float* __restrict__ feature1) {
    __shared__ float4 s2[GPTS];
    const int b   = blockIdx.y;
    const int tid = threadIdx.x;
    const int q   = tid & 7;                        // lane within point group
    const int n   = blockIdx.x * 32 + (tid >> 3);   // query point

    const float* c2 = coord2 + (size_t)b * 3 * GPTS;
    for (int g = tid; g < GPTS; g += 256) {
        float x = c2[g], y = c2[GPTS + g], z = c2[2 * GPTS + g];
        s2[g] = make_float4(x, y, z, -0.5f * (x * x + y * y + z * z));
    }
    __syncthreads();

    const float* c1 = coord1 + (size_t)b * 3 * NPTS;
    const float x = c1[n], y = c1[NPTS + n], z = c1[2 * NPTS + n];
    const float qn = x * x + y * y + z * z;

    // maximize e (3-best); e = x*cx + y*cy + z*cz - 0.5*|c|^2
    float e0 = -CUDART_INF_F, e1 = -CUDART_INF_F, e2 = -CUDART_INF_F;
    int   i0 = 0, i1 = 0, i2 = 0;
    #pragma unroll 4
    for (int it = 0; it < GPTS / 8; ++it) {
        const int g = q + it * 8;
        float4 c = s2[g];
        float e = fmaf(x, c.x, fmaf(y, c.y, fmaf(z, c.z, c.w)));
        if (e > e2) {
            if (e > e1) {
                e2 = e1; i2 = i1;
                if (e > e0) { e1 = e0; i1 = i0; e0 = e; i0 = g; }
                else        { e1 = e; i1 = g; }
            } else { e2 = e; i2 = g; }
        }
    }

    // butterfly merge of sorted top-3 lists across the 8 lanes (descending e)
    #pragma unroll
    for (int off = 1; off <= 4; off <<= 1) {
        float f0 = __shfl_xor_sync(0xffffffffu, e0, off);
        float f1 = __shfl_xor_sync(0xffffffffu, e1, off);
        float f2 = __shfl_xor_sync(0xffffffffu, e2, off);
        int   j0 = __shfl_xor_sync(0xffffffffu, i0, off);
        int   j1 = __shfl_xor_sync(0xffffffffu, i1, off);
        int   j2 = __shfl_xor_sync(0xffffffffu, i2, off);
        float m0, m1, m2; int k0, k1, k2;
        if (e0 >= f0) {
            m0 = e0; k0 = i0;
            if (e1 >= f0) {
                m1 = e1; k1 = i1;
                if (e2 >= f0) { m2 = e2; k2 = i2; } else { m2 = f0; k2 = j0; }
            } else {
                m1 = f0; k1 = j0;
                if (e1 >= f1) { m2 = e1; k2 = i1; } else { m2 = f1; k2 = j1; }
            }
        } else {
            m0 = f0; k0 = j0;
            if (f1 >= e0) {
                m1 = f1; k1 = j1;
                if (f2 >= e0) { m2 = f2; k2 = j2; } else { m2 = e0; k2 = i0; }
            } else {
                m1 = e0; k1 = i0;
                if (f1 >= e1) { m2 = f1; k2 = j1; } else { m2 = e1; k2 = i1; }
            }
        }
        e0 = m0; i0 = k0; e1 = m1; i1 = k1; e2 = m2; i2 = k2;
    }

    const float d0 = qn - 2.0f * e0;
    const float d1 = qn - 2.0f * e1;
    const float d2 = qn - 2.0f * e2;
    const float r0w = 1.0f / (d0 + 1e-8f);
    const float r1w = 1.0f / (d1 + 1e-8f);
    const float r2w = 1.0f / (d2 + 1e-8f);
    const float rs = 1.0f / (r0w + r1w + r2w);
    const float w0 = r0w * rs, w1 = r1w * rs, w2 = r2w * rs;

    const size_t row = (size_t)b * NPTS + n;
    uint4* hip = g_X1hi + row * (CIN / 8);
    uint4* lop = g_X1lo + row * (CIN / 8);

    // feature1 -> channels [0,128): lane q handles chunks q*2 .. q*2+1
    const float* f1 = feature1 + (size_t)b * D1 * NPTS + n;
    #pragma unroll
    for (int d8 = q * 2; d8 < q * 2 + 2; ++d8) {
        float v[8];
        #pragma unroll
        for (int j = 0; j < 8; ++j) v[j] = f1[(size_t)(d8 * 8 + j) * NPTS];
        split8_store(v, hip + d8, lop + d8);
    }

    // interp -> channels [128,384): lane q handles chunks q*4 .. q*4+3
    const float* F = g_f2t + (size_t)b * GPTS * D2;
    const float4* p0 = (const float4*)(F + (size_t)i0 * D2);
    const float4* p1 = (const float4*)(F + (size_t)i1 * D2);
    const float4* p2 = (const float4*)(F + (size_t)i2 * D2);
    #pragma unroll
    for (int d8 = q * 4; d8 < q * 4 + 4; ++d8) {
        float4 a0 = p0[2 * d8], a1 = p0[2 * d8 + 1];
        float4 b0 = p1[2 * d8], b1 = p1[2 * d8 + 1];
        float4 g0 = p2[2 * d8], g1 = p2[2 * d8 + 1];
        float v[8];
        v[0] = w0 * a0.x + w1 * b0.x + w2 * g0.x;
        v[1] = w0 * a0.y + w1 * b0.y + w2 * g0.y;
        v[2] = w0 * a0.z + w1 * b0.z + w2 * g0.z;
        v[3] = w0 * a0.w + w1 * b0.w + w2 * g0.w;
        v[4] = w0 * a1.x + w1 * b1.x + w2 * g1.x;
        v[5] = w0 * a1.y + w1 * b1.y + w2 * g1.y;
        v[6] = w0 * a1.z + w1 * b1.z + w2 * g1.z;
        v[7] = w0 * a1.w + w1 * b1.w + w2 * g1.w;
        split8_store(v, hip + D1 / 8 + d8, lop + D1 / 8 + d8);
    }
}

// ======================= HMMA GEMM (cp.async double-buffered) ===============
// C[m][n] = sum_k W[m][k] * X[n][k], split: Whi*Xhi + Whi*Xlo + Wlo*Xhi.
// CTA tile 128(M)x128(N), K-chunk 64, 2-stage pipeline. 8 warps = 2(M)x4(N).
// Epilogue: Yt[n][m] = acc + bias[m]; BN stats (sum/sumsq) fused via RED.
template <int LAYER>
__global__ void __launch_bounds__(256, 2)
gemm_mma_kernel(const float* __restrict__ bias) {
    constexpr int K0 = (LAYER == 1) ? CIN : CH;
    constexpr int KC = K0 / 64;
    constexpr int NC = 3 * KC;

    const __nv_bfloat16* Whi = (LAYER == 1) ? (const __nv_bfloat16*)g_W1hi
                                            : (const __nv_bfloat16*)g_W2hi;
    const __nv_bfloat16* Wlo = (LAYER == 1) ? (const __nv_bfloat16*)g_W1lo
                                            : (const __nv_bfloat16*)g_W2lo;
    const __nv_bfloat16* Xhi = (LAYER == 1) ? (const __nv_bfloat16*)g_X1hi
                                            : (const __nv_bfloat16*)g_X2hi;
    const __nv_bfloat16* Xlo = (LAYER == 1) ? (const __nv_bfloat16*)g_X1lo
                                            : (const __nv_bfloat16*)g_X2lo;
    float* Yt    = (LAYER == 1) ? g_Y1t : g_Y2t;
    float* gsum  = (LAYER == 1) ? g_sum1 : g_sum2;
    float* gsq   = (LAYER == 1) ? g_sumsq1 : g_sumsq2;

    __shared__ __align__(16) __nv_bfloat16 sA[2][128 * SROW];
    __shared__ __align__(16) __nv_bfloat16 sB[2][128 * SROW];

    const int tid  = threadIdx.x;
    const int wid  = tid >> 5, lane = tid & 31;
    const int tg   = lane >> 2;            // groupID (0..7)
    const int tig  = lane & 3;             // threadID_in_group (0..3)
    const size_t r0 = (size_t)blockIdx.x * 128;   // X row block
    const int m0 = blockIdx.y * 128;              // W row block
    const int wm = (wid & 1) * 64;
    const int wn = (wid >> 1) * 32;

    const uint32_t saA = smem_u32(sA);
    const uint32_t saB = smem_u32(sB);
    const int ldr  = tid >> 3;             // load row (0..31 step per iter)
    const int ldch = tid & 7;              // 16B chunk in row
    const uint32_t ldoff = (uint32_t)(ldr * SROW + ldch * 8) * 2;

    float acc[4][4][4];
    #pragma unroll
    for (int i = 0; i < 4; ++i)
        #pragma unroll
        for (int j = 0; j < 4; ++j)
            #pragma unroll
            for (int k = 0; k < 4; ++k) acc[i][j][k] = 0.f;

    auto issue = [&](int c, int st) {
        const int phase = c / KC;
        const int kk = (c - phase * KC) * 64;
        const __nv_bfloat16* Asrc = (phase < 2) ? Whi : Wlo;
        const __nv_bfloat16* Bsrc = ((phase == 1) ? Xlo : Xhi);
        const uint32_t baseA = saA + (uint32_t)st * TILEB + ldoff;
        const uint32_t baseB = saB + (uint32_t)st * TILEB + ldoff;
        #pragma unroll
        for (int i = 0; i < 4; ++i) {
            const int r = ldr + i * 32;
            CPA16(baseA + (uint32_t)(i * 32 * SROW * 2),
                  Asrc + (size_t)(m0 + r) * K0 + kk + ldch * 8);
            CPA16(baseB + (uint32_t)(i * 32 * SROW * 2),
                  Bsrc + (r0 + r) * K0 + kk + ldch * 8);
        }
        CP_COMMIT();
    };

    issue(0, 0);
    for (int c = 0; c < NC; ++c) {
        const int st = c & 1;
        if (c + 1 < NC) { issue(c + 1, st ^ 1); CP_WAIT1(); }
        else            { CP_WAIT0(); }
        __syncthreads();

        const __nv_bfloat16* A = sA[st];
        const __nv_bfloat16* B = sB[st];
        #pragma unroll
        for (int ks = 0; ks < 4; ++ks) {      // k16 steps within 64-chunk
            const int kb = ks * 16;
            uint32_t b[4][2];
            #pragma unroll
            for (int ni = 0; ni < 4; ++ni) {
                const int rb = (wn + ni * 8 + tg) * SROW;
                b[ni][0] = *(const uint32_t*)(&B[rb + kb + 2 * tig]);
                b[ni][1] = *(const uint32_t*)(&B[rb + kb + 8 + 2 * tig]);
            }
            #pragma unroll
            for (int mi = 0; mi < 4; ++mi) {
                const int ra0 = (wm + mi * 16 + tg) * SROW;
                const int ra1 = ra0 + 8 * SROW;
                uint32_t a0 = *(const uint32_t*)(&A[ra0 + kb + 2 * tig]);
                uint32_t a1 = *(const uint32_t*)(&A[ra1 + kb + 2 * tig]);
                uint32_t a2 = *(const uint32_t*)(&A[ra0 + kb + 8 + 2 * tig]);
                uint32_t a3 = *(const uint32_t*)(&A[ra1 + kb + 8 + 2 * tig]);
                #pragma unroll
                for (int ni = 0; ni < 4; ++ni)
                    mma16816(acc[mi][ni], a0, a1, a2, a3, b[ni][0], b[ni][1]);
            }
        }
        __syncthreads();
    }

    // epilogue: store + fused BN stats
    #pragma unroll
    for (int mi = 0; mi < 4; ++mi) {
        const int mg0 = m0 + wm + mi * 16 + tg;
        const int mg1 = mg0 + 8;
        const float bv0 = bias[mg0];
        const float bv1 = bias[mg1];
        float s0 = 0.f, q0 = 0.f, s1 = 0.f, q1 = 0.f;
        #pragma unroll
        for (int ni = 0; ni < 4; ++ni) {
            const size_t n = r0 + wn + ni * 8 + 2 * tig;
            const float v00 = acc[mi][ni][0] + bv0;
            const float v01 = acc[mi][ni][1] + bv0;
            const float v10 = acc[mi][ni][2] + bv1;
            const float v11 = acc[mi][ni][3] + bv1;
            Yt[n * 256 + mg0]       = v00;
            Yt[(n + 1) * 256 + mg0] = v01;
            Yt[n * 256 + mg1]       = v10;
            Yt[(n + 1) * 256 + mg1] = v11;
            s0 += v00 + v01; q0 += v00 * v00 + v01 * v01;
            s1 += v10 + v11; q1 += v10 * v10 + v11 * v11;
        }
        #pragma unroll
        for (int off = 1; off <= 2; off <<= 1) {
            s0 += __shfl_xor_sync(0xffffffffu, s0, off);
            q0 += __shfl_xor_sync(0xffffffffu, q0, off);
            s1 += __shfl_xor_sync(0xffffffffu, s1, off);
            q1 += __shfl_xor_sync(0xffffffffu, q1, off);
        }
        if (tig == 0) {
            atomicAdd(&gsum[mg0], s0); atomicAdd(&gsq[mg0], q0);
            atomicAdd(&gsum[mg1], s1); atomicAdd(&gsq[mg1], q1);
        }
    }
}

// ======================= finalize / fold ====================================
template <int LAYER>
__global__ void finalize_kernel(const float* __restrict__ gamma,
                                const float* __restrict__ beta) {
    const float* gsum = (LAYER == 1) ? g_sum1 : g_sum2;
    const float* gsq  = (LAYER == 1) ? g_sumsq1 : g_sumsq2;
    float* scale      = (LAYER == 1) ? g_scale1 : g_scale2;
    float* shift      = (LAYER == 1) ? g_shift1 : g_shift2;
    const int c = threadIdx.x;
    const float inv = 1.0f / (float)((size_t)NT);
    float m  = gsum[c] * inv;
    float v  = fmaxf(gsq[c] * inv - m * m, 0.f);
    float sc = gamma[c] * rsqrtf(v + BN_EPS);
    scale[c] = sc;
    shift[c] = beta[c] - m * sc;
}

// BN1 + ReLU + bf16 split: Y1t [row][256] -> X2hi/X2lo [row][256]
__global__ void convert2_kernel() {
    const int gid = blockIdx.x * 256 + threadIdx.x;       // one per 8 channels
    const size_t r = (size_t)(gid >> 5);
    const int c0 = (gid & 31) * 8;
    const float* p = g_Y1t + r * 256 + c0;
    float4 a = *(const float4*)(p);
    float4 b = *(const float4*)(p + 4);
    float4 s0 = *(const float4*)(g_scale1 + c0);
    float4 s1 = *(const float4*)(g_scale1 + c0 + 4);
    float4 t0 = *(const float4*)(g_shift1 + c0);
    float4 t1 = *(const float4*)(g_shift1 + c0 + 4);
    float v[8];
    v[0] = fmaxf(fmaf(a.x, s0.x, t0.x), 0.f);
    v[1] = fmaxf(fmaf(a.y, s0.y, t0.y), 0.f);
    v[2] = fmaxf(fmaf(a.z, s0.z, t0.z), 0.f);
    v[3] = fmaxf(fmaf(a.w, s0.w, t0.w), 0.f);
    v[4] = fmaxf(fmaf(b.x, s1.x, t1.x), 0.f);
    v[5] = fmaxf(fmaf(b.y, s1.y, t1.y), 0.f);
    v[6] = fmaxf(fmaf(b.z, s1.z, t1.z), 0.f);
    v[7] = fmaxf(fmaf(b.w, s1.w, t1.w), 0.f);
    split8_store(v, g_X2hi + (r * 256 + c0) / 8, g_X2lo + (r * 256 + c0) / 8);
}

// final: Y2t [row n][m] -> out [b][m][n] with BN2 + ReLU
__global__ void transpose_out_kernel(float* __restrict__ out) {
    __shared__ float tile[32][33];
    const int r0 = blockIdx.x * 32;     // flat row (b*N + n)
    const int c0 = blockIdx.y * 32;     // channel
    #pragma unroll
    for (int i = threadIdx.y; i < 32; i += 8)
        tile[i][threadIdx.x] = g_Y2t[(size_t)(r0 + i) * 256 + c0 + threadIdx.x];
    __syncthreads();
    const int b  = r0 >> 12;
    const int n0 = r0 & (NPTS - 1);
    #pragma unroll
    for (int i = threadIdx.y; i < 32; i += 8) {
        int c = c0 + i;
        float s = g_scale2[c], t = g_shift2[c];
        out[((size_t)b * 256 + c) * NPTS + n0 + threadIdx.x] =
            fmaxf(fmaf(tile[threadIdx.x][i], s, t), 0.f);
    }
}

// ======================= launch =============================================
extern "C" void kernel_launch(void* const* d_in, const int* in_sizes, int n_in,
                              void* d_out, int out_size) {
    const float* feature1 = (const float*)d_in[0];
    const float* coord1   = (const float*)d_in[1];
    const float* feature2 = (const float*)d_in[2];
    const float* coord2   = (const float*)d_in[3];
    const float* W1 = (const float*)d_in[4];
    const float* b1 = (const float*)d_in[5];
    const float* gamma1 = (const float*)d_in[6];
    const float* beta1  = (const float*)d_in[7];
    const float* W2 = (const float*)d_in[8];
    const float* b2 = (const float*)d_in[9];
    const float* gamma2 = (const float*)d_in[10];
    const float* beta2  = (const float*)d_in[11];
    float* out = (float*)d_out;

    init_kernel<<<1, 256>>>();
    convert_w_kernel<<<(CH * CIN + COUT * CH + 255) / 256, 256>>>(W1, W2);
    transpose_f2_kernel<<<dim3(GPTS / 32, D2 / 32, BATCH), dim3(32, 8)>>>(feature2);
    knn_interp_kernel<<<dim3(NPTS / 32, BATCH), 256>>>(coord1, coord2, feature1);

    gemm_mma_kernel<1><<<dim3(NT / 128, 2), 256>>>(b1);
    finalize_kernel<1><<<1, CH>>>(gamma1, beta1);
    convert2_kernel<<<NT * 32 / 256, 256>>>();

    gemm_mma_kernel<2><<<dim3(NT / 128, 2), 256>>>(b2);
    finalize_kernel<2><<<1, COUT>>>(gamma2, beta2);

    transpose_out_kernel<<<dim3(NT / 32, 256 / 32), dim3(32, 8)>>>(out);
}